// round 13
// baseline (speedup 1.0000x reference)
#include <cuda_runtime.h>
#include <cuda_bf16.h>
#include <cstdint>
#include <math.h>

#define T_STEPS 256
#define INPUT   12288
#define HID     1024
#define GATES   4096

// ---------------- device scratch (no allocations allowed) ----------------
__device__ unsigned long long g_hp[2][HID];        // {epoch|h} ping-pong
__device__ __nv_bfloat16 g_Ahi[T_STEPS * INPUT];   // frames bf16 hi
__device__ __nv_bfloat16 g_Alo[T_STEPS * INPUT];   // frames bf16 lo

// ---------------- helpers ----------------
__device__ __forceinline__ void ffma2(unsigned long long& d,
                                      unsigned long long a,
                                      unsigned long long b) {
    asm("fma.rn.f32x2 %0, %1, %2, %0;" : "+l"(d) : "l"(a), "l"(b));
}
__device__ __forceinline__ void unpack2(unsigned long long v, float& lo, float& hi) {
    asm("mov.b64 {%0, %1}, %2;" : "=f"(lo), "=f"(hi) : "l"(v));
}
__device__ __forceinline__ unsigned int pack2f(float a, float b) {
    __nv_bfloat162 t = __floats2bfloat162_rn(a, b);
    return *reinterpret_cast<unsigned int*>(&t);
}
__device__ __forceinline__ void cvt_pair(float f0, float f1,
                                         unsigned int& h01, unsigned int& l01) {
    h01 = pack2f(f0, f1);
    float h0 = __uint_as_float(h01 << 16);
    float h1 = __uint_as_float(h01 & 0xFFFF0000u);
    l01 = pack2f(f0 - h0, f1 - h1);
}
__device__ __forceinline__ void mma_bf16(float c[4], const uint32_t a[4],
                                         const uint32_t b[2]) {
    asm volatile(
        "mma.sync.aligned.m16n8k16.row.col.f32.bf16.bf16.f32 "
        "{%0,%1,%2,%3}, {%4,%5,%6,%7}, {%8,%9}, {%0,%1,%2,%3};"
        : "+f"(c[0]), "+f"(c[1]), "+f"(c[2]), "+f"(c[3])
        : "r"(a[0]), "r"(a[1]), "r"(a[2]), "r"(a[3]), "r"(b[0]), "r"(b[1]));
}
__device__ __forceinline__ unsigned long long ld_rlx(const unsigned long long* p) {
    unsigned long long v;
    asm volatile("ld.relaxed.gpu.global.u64 %0, [%1];" : "=l"(v) : "l"(p) : "memory");
    return v;
}
__device__ __forceinline__ void st_rlx(unsigned long long* p, unsigned long long v) {
    asm volatile("st.relaxed.gpu.global.u64 [%0], %1;" :: "l"(p), "l"(v) : "memory");
}
__device__ __forceinline__ float fast_sigmoid(float x) {
    return __fdividef(1.f, 1.f + __expf(-x));
}
__device__ __forceinline__ float fast_tanh(float x) {
    float e = __expf(-2.f * x);
    return __fdividef(1.f - e, 1.f + e);
}

// ---------------- init ----------------
__global__ void init_kernel() {
    int tid = blockIdx.x * blockDim.x + threadIdx.x;
    if (tid < HID) {
        g_hp[0][tid] = 0ULL;
        g_hp[1][tid] = 0ULL;
    }
}

// ---------------- split A: fp32 -> bf16 hi + lo ----------------
__global__ __launch_bounds__(256)
void splitA_kernel(const float* __restrict__ A) {
    const int NA = T_STEPS * INPUT / 4;
    int stride = gridDim.x * blockDim.x;
    for (int i = blockIdx.x * blockDim.x + threadIdx.x; i < NA; i += stride) {
        float4 v = ((const float4*)A)[i];
        uint2 hi, lo;
        cvt_pair(v.x, v.y, hi.x, lo.x);
        cvt_pair(v.z, v.w, hi.y, lo.y);
        ((uint2*)g_Ahi)[i] = hi;
        ((uint2*)g_Alo)[i] = lo;
    }
}

// ---------------- fused GEMM + scan kernel ----------------
// 128 CTAs x 256 threads. CTA b: scan units j = 8b..8b+7 (warp w <-> unit);
// GEMM: its own 32 gate columns (rows g*1024 + 8b + u of W_ih) for all 256 t.
// Groups of k=128 (4 chunks x k32); 768 groups total; 3 per scan step after a
// 99-group prologue folded into step 0. xp lives in smem.
#define ROWB   272                    // staged row bytes (256 data + 16 pad)
#define MAT_B  (32 * ROWB)            // 8704
#define STG_B  (4 * MAT_B)            // 34816 per stage (Ah, Al, Bh, Bl)
#define XP_P   33                     // xp row pitch (floats)
#define SM_XP    0
#define SM_STAGE 33792                // 256*33*4
#define SM_HS    (SM_STAGE + 2 * STG_B)      // 103424
#define SM_BIAS  (SM_HS + 2 * HID * 4)       // 111616
#define FUSED_SMEM (SM_BIAS + 128)           // 111744
#define NGROUPS 768

__global__ __launch_bounds__(256, 1)
void fused_kernel(const float* __restrict__ W,      // W_ih
                  const float* __restrict__ Whh,
                  const float* __restrict__ b_ih,
                  const float* __restrict__ b_hh) {
    extern __shared__ char smem[];
    float* xp     = (float*)(smem + SM_XP);
    char*  stg    = smem + SM_STAGE;
    float* hsbuf  = (float*)(smem + SM_HS);
    float* bias_s = (float*)(smem + SM_BIAS);

    const int tid  = threadIdx.x;
    const int warp = tid >> 5;
    const int lane = tid & 31;
    const int g    = lane >> 2;
    const int tg   = lane & 3;
    const int b    = blockIdx.x;
    const int j    = b * 8 + warp;          // scan unit
    const int wm   = (warp & 1) * 16;       // gemm warp tile m offset
    const int wn   = (warp >> 1) * 8;       // gemm warp tile n offset

    // biases for this CTA's 32 columns
    if (tid < 32) {
        int gg = tid >> 3, u = tid & 7;
        int gidx = gg * 1024 + b * 8 + u;
        bias_s[tid] = b_ih[gidx] + b_hh[gidx];
    }

    // W_hh fragment in registers (R5/R11-validated)
    unsigned long long wreg[4][8][2];
#pragma unroll
    for (int gg = 0; gg < 4; gg++) {
        const float* wrow = Whh + (size_t)(gg * HID + j) * HID;
#pragma unroll
        for (int i = 0; i < 8; i++) {
            ulonglong2 v = *(const ulonglong2*)&wrow[lane * 4 + i * 128];
            wreg[gg][i][0] = v.x;
            wreg[gg][i][1] = v.y;
        }
    }

    // ---- GEMM load-index mapping (fixed per thread) ----
    int rA[2], kcA[2];
#pragma unroll
    for (int p = 0; p < 2; p++) {
        int idx = tid + p * 256;
        rA[p] = idx >> 4; kcA[p] = idx & 15;   // 32 rows x 16 uint4
    }
    int rB[4], cB4[4], gRow[4];
#pragma unroll
    for (int p = 0; p < 4; p++) {
        int idx = tid + p * 256;
        rB[p] = idx >> 5; cB4[p] = idx & 31;   // 32 rows x 32 float4
        gRow[p] = (rB[p] >> 3) * 1024 + b * 8 + (rB[p] & 7);
    }

    uint4 pAh[2], pAl[2];
    float4 pB[4];
    float acc[4] = {0.f, 0.f, 0.f, 0.f};

    // ---- pre-stage group 0 ----
#pragma unroll
    for (int p = 0; p < 2; p++) {
        size_t off = (size_t)rA[p] * INPUT + kcA[p] * 8;
        pAh[p] = *(const uint4*)(g_Ahi + off);
        pAl[p] = *(const uint4*)(g_Alo + off);
    }
#pragma unroll
    for (int p = 0; p < 4; p++)
        pB[p] = *(const float4*)(W + (size_t)gRow[p] * INPUT + cB4[p] * 4);
    {
        char* s0 = stg;
#pragma unroll
        for (int p = 0; p < 2; p++) {
            uint32_t d = rA[p] * ROWB + kcA[p] * 16;
            *(uint4*)(s0 + d) = pAh[p];
            *(uint4*)(s0 + MAT_B + d) = pAl[p];
        }
#pragma unroll
        for (int p = 0; p < 4; p++) {
            uint2 h, l;
            cvt_pair(pB[p].x, pB[p].y, h.x, l.x);
            cvt_pair(pB[p].z, pB[p].w, h.y, l.y);
            uint32_t e = rB[p] * ROWB + cB4[p] * 8;
            *(uint2*)(s0 + 2 * MAT_B + e) = h;
            *(uint2*)(s0 + 3 * MAT_B + e) = l;
        }
    }

    int gdone = 0;
    float cstate = 0.f;

    for (int t = 0; t < T_STEPS; t++) {
        // ---- GEMM phase: advance to schedule target ----
        int gt = 99 + 3 * t;
        if (gt > NGROUPS) gt = NGROUPS;
        while (gdone < gt) {
            __syncthreads();   // stage[gdone&1] visible; prior reads of other stage done
            const int cur = gdone & 1;
            const bool pf = (gdone + 1 < NGROUPS);
            if (pf) {
                int gn = gdone + 1;
                int mbN = gn / 96;
                int k0N = (gn % 96) * 128;
#pragma unroll
                for (int p = 0; p < 2; p++) {
                    size_t off = (size_t)(mbN * 32 + rA[p]) * INPUT + k0N + kcA[p] * 8;
                    pAh[p] = *(const uint4*)(g_Ahi + off);
                    pAl[p] = *(const uint4*)(g_Alo + off);
                }
#pragma unroll
                for (int p = 0; p < 4; p++)
                    pB[p] = *(const float4*)(W + (size_t)gRow[p] * INPUT + k0N + cB4[p] * 4);
            }
            // compute 8 k16 steps on stage cur
            const char* sa = stg + cur * STG_B;
#pragma unroll
            for (int ck = 0; ck < 8; ck++) {
                const uint32_t off = ck * 32 + tg * 4;
                uint32_t ah[4], al[4], bh[2], bl[2];
                uint32_t ra = (wm + g) * ROWB + off;
                ah[0] = *(const uint32_t*)(sa + ra);
                ah[1] = *(const uint32_t*)(sa + ra + 8 * ROWB);
                ah[2] = *(const uint32_t*)(sa + ra + 16);
                ah[3] = *(const uint32_t*)(sa + ra + 8 * ROWB + 16);
                al[0] = *(const uint32_t*)(sa + MAT_B + ra);
                al[1] = *(const uint32_t*)(sa + MAT_B + ra + 8 * ROWB);
                al[2] = *(const uint32_t*)(sa + MAT_B + ra + 16);
                al[3] = *(const uint32_t*)(sa + MAT_B + ra + 8 * ROWB + 16);
                uint32_t rb = (wn + g) * ROWB + off;
                bh[0] = *(const uint32_t*)(sa + 2 * MAT_B + rb);
                bh[1] = *(const uint32_t*)(sa + 2 * MAT_B + rb + 16);
                bl[0] = *(const uint32_t*)(sa + 3 * MAT_B + rb);
                bl[1] = *(const uint32_t*)(sa + 3 * MAT_B + rb + 16);
                mma_bf16(acc, ah, bh);
                mma_bf16(acc, ah, bl);
                mma_bf16(acc, al, bh);
            }
            // STS prefetched group into the other stage
            if (pf) {
                char* sn = stg + ((gdone + 1) & 1) * STG_B;
#pragma unroll
                for (int p = 0; p < 2; p++) {
                    uint32_t d = rA[p] * ROWB + kcA[p] * 16;
                    *(uint4*)(sn + d) = pAh[p];
                    *(uint4*)(sn + MAT_B + d) = pAl[p];
                }
#pragma unroll
                for (int p = 0; p < 4; p++) {
                    uint2 h, l;
                    cvt_pair(pB[p].x, pB[p].y, h.x, l.x);
                    cvt_pair(pB[p].z, pB[p].w, h.y, l.y);
                    uint32_t e = rB[p] * ROWB + cB4[p] * 8;
                    *(uint2*)(sn + 2 * MAT_B + e) = h;
                    *(uint2*)(sn + 3 * MAT_B + e) = l;
                }
            }
            gdone++;
            if ((gdone % 96) == 0) {
                // block epilogue: acc -> xp (+bias), reset acc
                int mb = gdone / 96 - 1;
                int t0 = mb * 32 + wm + g;
                int nl = wn + tg * 2;
                float bi0 = bias_s[nl], bi1 = bias_s[nl + 1];
                xp[t0 * XP_P + nl]           = acc[0] + bi0;
                xp[t0 * XP_P + nl + 1]       = acc[1] + bi1;
                xp[(t0 + 8) * XP_P + nl]     = acc[2] + bi0;
                xp[(t0 + 8) * XP_P + nl + 1] = acc[3] + bi1;
                acc[0] = acc[1] = acc[2] = acc[3] = 0.f;
            }
        }

        // ---- scan step t: acquire h_t (payload epochs, busy spin) ----
        const unsigned long long* p0 = g_hp[t & 1] + tid;
        const unsigned int want = (unsigned int)t;
        unsigned long long v0, v1, v2, v3;
        bool ok;
        do {
            v0 = ld_rlx(p0);
            v1 = ld_rlx(p0 + 256);
            v2 = ld_rlx(p0 + 512);
            v3 = ld_rlx(p0 + 768);
            ok = ((unsigned int)(v0 >> 32) == want) &
                 ((unsigned int)(v1 >> 32) == want) &
                 ((unsigned int)(v2 >> 32) == want) &
                 ((unsigned int)(v3 >> 32) == want);
        } while (!ok);
        float* hcur = hsbuf + (t & 1) * HID;
        hcur[tid]       = __uint_as_float((unsigned int)v0);
        hcur[tid + 256] = __uint_as_float((unsigned int)v1);
        hcur[tid + 512] = __uint_as_float((unsigned int)v2);
        hcur[tid + 768] = __uint_as_float((unsigned int)v3);
        __syncthreads();

        // x_proj gates from smem xp (broadcast reads)
        float xg0 = xp[t * XP_P + warp];
        float xg1 = xp[t * XP_P + 8 + warp];
        float xg2 = xp[t * XP_P + 16 + warp];
        float xg3 = xp[t * XP_P + 24 + warp];

        // gate matvec (W in regs, h in smem)
        unsigned long long a2[4] = {0ULL, 0ULL, 0ULL, 0ULL};
#pragma unroll
        for (int i = 0; i < 8; i++) {
            ulonglong2 h2 = *(const ulonglong2*)&hcur[lane * 4 + i * 128];
#pragma unroll
            for (int gg = 0; gg < 4; gg++) {
                ffma2(a2[gg], h2.x, wreg[gg][i][0]);
                ffma2(a2[gg], h2.y, wreg[gg][i][1]);
            }
        }
        float red[4];
#pragma unroll
        for (int gg = 0; gg < 4; gg++) {
            float lo, hi;
            unpack2(a2[gg], lo, hi);
            red[gg] = lo + hi;
        }
#pragma unroll
        for (int o = 16; o; o >>= 1) {
#pragma unroll
            for (int gg = 0; gg < 4; gg++)
                red[gg] += __shfl_xor_sync(0xffffffffu, red[gg], o);
        }

        float gi = fast_sigmoid(xg0 + red[0]);
        float gf = fast_sigmoid(xg1 + red[1]);
        float gG = fast_tanh(xg2 + red[2]);
        float go = fast_sigmoid(xg3 + red[3]);
        cstate = gf * cstate + gi * gG;
        float hnew = go * fast_tanh(cstate);

        if (lane == 0) {
            unsigned long long pk =
                ((unsigned long long)(unsigned int)(t + 1) << 32) |
                (unsigned long long)__float_as_uint(hnew);
            st_rlx(&g_hp[(t + 1) & 1][j], pk);
        }
    }
}

// ---------------- final: out = h_T @ fc_w^T + fc_b ----------------
__global__ __launch_bounds__(256, 2)
void final_kernel(const float* __restrict__ fcw,
                  const float* __restrict__ fcb,
                  float* __restrict__ out) {
    __shared__ float hs[HID];
    const int tid = threadIdx.x, warp = tid >> 5, lane = tid & 31;
#pragma unroll
    for (int q = 0; q < 4; q++)
        hs[tid + q * 256] = __uint_as_float((unsigned int)g_hp[0][tid + q * 256]);
    __syncthreads();

    int row = blockIdx.x * 16 + warp * 2;
    const float* wr0 = fcw + (size_t)row * HID;
    const float* wr1 = wr0 + HID;
    float acc0 = 0.f, acc1 = 0.f;
#pragma unroll
    for (int i = 0; i < 8; i++) {
        float4 h4 = *(const float4*)&hs[lane * 4 + i * 128];
        float4 a4 = *(const float4*)&wr0[lane * 4 + i * 128];
        float4 b4 = *(const float4*)&wr1[lane * 4 + i * 128];
        acc0 += a4.x * h4.x + a4.y * h4.y + a4.z * h4.z + a4.w * h4.w;
        acc1 += b4.x * h4.x + b4.y * h4.y + b4.z * h4.z + b4.w * h4.w;
    }
#pragma unroll
    for (int o = 16; o; o >>= 1) {
        acc0 += __shfl_xor_sync(0xffffffffu, acc0, o);
        acc1 += __shfl_xor_sync(0xffffffffu, acc1, o);
    }
    if (lane == 0) {
        out[row]     = acc0 + fcb[row];
        out[row + 1] = acc1 + fcb[row + 1];
    }
}

// ---------------- launch ----------------
extern "C" void kernel_launch(void* const* d_in, const int* in_sizes, int n_in,
                              void* d_out, int out_size) {
    const float* frames = (const float*)d_in[0];
    const float* W_ih   = (const float*)d_in[1];
    const float* W_hh   = (const float*)d_in[2];
    const float* b_ih   = (const float*)d_in[3];
    const float* b_hh   = (const float*)d_in[4];
    const float* fc_w   = (const float*)d_in[5];
    const float* fc_b   = (const float*)d_in[6];
    float* out = (float*)d_out;

    cudaFuncSetAttribute(fused_kernel,
                         cudaFuncAttributeMaxDynamicSharedMemorySize, FUSED_SMEM);

    init_kernel<<<4, 256>>>();

    splitA_kernel<<<1024, 256>>>(frames);

    fused_kernel<<<128, 256, FUSED_SMEM>>>(W_ih, W_hh, b_ih, b_hh);

    final_kernel<<<12288 / 16, 256>>>(fc_w, fc_b, out);
}

// round 14
// speedup vs baseline: 1.1514x; 1.1514x over previous
#include <cuda_runtime.h>
#include <cuda_fp16.h>
#include <cstdint>
#include <math.h>

#define T_STEPS 256
#define INPUT   12288
#define HID     1024
#define GATES   4096

#define LO_SCALE 2048.0f
#define INV_LO   (1.0f / 2048.0f)

// ---------------- device scratch (no allocations allowed) ----------------
__device__ float              g_xproj[T_STEPS * GATES];  // 4 MB
__device__ unsigned long long g_hp[2][HID];              // {epoch|h} ping-pong
// fp16 hi + scaled-lo split of A (frames); W split in-kernel
__device__ __half g_Ahi[T_STEPS * INPUT];
__device__ __half g_Alo[T_STEPS * INPUT];

// ---------------- helpers: packed f32x2 FMA (scan) ----------------
__device__ __forceinline__ void ffma2(unsigned long long& d,
                                      unsigned long long a,
                                      unsigned long long b) {
    asm("fma.rn.f32x2 %0, %1, %2, %0;" : "+l"(d) : "l"(a), "l"(b));
}
__device__ __forceinline__ void unpack2(unsigned long long v, float& lo, float& hi) {
    asm("mov.b64 {%0, %1}, %2;" : "=f"(lo), "=f"(hi) : "l"(v));
}

// ---------------- init ----------------
__global__ void init_kernel() {
    int tid = blockIdx.x * blockDim.x + threadIdx.x;
    if (tid < HID) {
        g_hp[0][tid] = 0ULL;
        g_hp[1][tid] = 0ULL;
    }
}

// ---------------- fp16 split: hi = f16(x), lo = f16((x - hi) * 2048) ----------------
__device__ __forceinline__ void cvt_pair_h(float f0, float f1,
                                           unsigned int& h01, unsigned int& l01) {
    __half2 h = __floats2half2_rn(f0, f1);
    float e0 = (f0 - __half2float(__low2half(h)))  * LO_SCALE;
    float e1 = (f1 - __half2float(__high2half(h))) * LO_SCALE;
    __half2 l = __floats2half2_rn(e0, e1);
    h01 = *reinterpret_cast<unsigned int*>(&h);
    l01 = *reinterpret_cast<unsigned int*>(&l);
}
__global__ __launch_bounds__(256)
void splitA_kernel(const float* __restrict__ A) {
    const int NA = T_STEPS * INPUT / 4;
    int stride = gridDim.x * blockDim.x;
    for (int i = blockIdx.x * blockDim.x + threadIdx.x; i < NA; i += stride) {
        float4 v = ((const float4*)A)[i];
        uint2 hi, lo;
        cvt_pair_h(v.x, v.y, hi.x, lo.x);
        cvt_pair_h(v.z, v.w, hi.y, lo.y);
        ((uint2*)g_Ahi)[i] = hi;
        ((uint2*)g_Alo)[i] = lo;
    }
}

// ---------------- fused mma GEMM: x_proj = frames @ W_ih^T + biases ----------------
// CTA tile 128m x 64n, grid (64, 2). A pre-split fp16; W split in-kernel.
// Per k16: hh (f32 acc, exact main) + [hl + lh] (shared f16 acc, scaled 2048).
#define GK 32
#define NCH (INPUT / GK)        // 384 chunks
#define A_MAT_B (128 * 80)      // 10240 B (128 rows x 80B padded)
#define B_MAT_B (64 * 80)       //  5120 B
#define STAGE_B (2 * A_MAT_B + 2 * B_MAT_B)   // 30720
#define GEMM_SMEM (2 * STAGE_B)               // 61440
#define OFF_AH 0
#define OFF_AL A_MAT_B
#define OFF_BH (2 * A_MAT_B)
#define OFF_BL (2 * A_MAT_B + B_MAT_B)

__device__ __forceinline__ uint32_t smem_u32(const void* p) {
    uint32_t a;
    asm("{ .reg .u64 t; cvta.to.shared.u64 t, %1; cvt.u32.u64 %0, t; }" : "=r"(a) : "l"(p));
    return a;
}
__device__ __forceinline__ void lm4(uint32_t& d0, uint32_t& d1, uint32_t& d2,
                                    uint32_t& d3, uint32_t addr) {
    asm volatile("ldmatrix.sync.aligned.m8n8.x4.shared.b16 {%0,%1,%2,%3}, [%4];"
                 : "=r"(d0), "=r"(d1), "=r"(d2), "=r"(d3) : "r"(addr));
}
__device__ __forceinline__ void mma_f16_f32acc(float c[4], const uint32_t a[4],
                                               const uint32_t b[2]) {
    asm volatile(
        "mma.sync.aligned.m16n8k16.row.col.f32.f16.f16.f32 "
        "{%0,%1,%2,%3}, {%4,%5,%6,%7}, {%8,%9}, {%0,%1,%2,%3};"
        : "+f"(c[0]), "+f"(c[1]), "+f"(c[2]), "+f"(c[3])
        : "r"(a[0]), "r"(a[1]), "r"(a[2]), "r"(a[3]), "r"(b[0]), "r"(b[1]));
}
__device__ __forceinline__ void mma_f16_f16acc(uint32_t c[2], const uint32_t a[4],
                                               const uint32_t b[2]) {
    asm volatile(
        "mma.sync.aligned.m16n8k16.row.col.f16.f16.f16.f16 "
        "{%0,%1}, {%2,%3,%4,%5}, {%6,%7}, {%0,%1};"
        : "+r"(c[0]), "+r"(c[1])
        : "r"(a[0]), "r"(a[1]), "r"(a[2]), "r"(a[3]), "r"(b[0]), "r"(b[1]));
}

__global__ __launch_bounds__(256, 1)
void gemm_fused_kernel(const float* __restrict__ W,
                       const float* __restrict__ b_ih,
                       const float* __restrict__ b_hh) {
    extern __shared__ char smem[];
    const uint32_t sbase = smem_u32(smem);
    const int tid  = threadIdx.x;
    const int warp = tid >> 5;
    const int lane = tid & 31;
    const int g    = lane >> 2;
    const int tg   = lane & 3;
    const int n0   = blockIdx.x * 64;
    const int m0   = blockIdx.y * 128;
    const int wm   = (warp & 3) * 32;
    const int wn   = (warp >> 2) * 32;

    float    acc [2][4][4];   // main hh, f32
    uint32_t accC[2][4][2];   // corrections, f16x2 pairs
#pragma unroll
    for (int i = 0; i < 2; i++)
#pragma unroll
        for (int jn = 0; jn < 4; jn++) {
#pragma unroll
            for (int q = 0; q < 4; q++) acc[i][jn][q] = 0.f;
            accC[i][jn][0] = 0u; accC[i][jn][1] = 0u;
        }

    // ldmatrix per-lane offsets (validated in R11)
    const uint32_t aOff = (uint32_t)((wm + ((lane >> 3) & 1) * 8 + (lane & 7)) * 80
                                     + (lane >> 4) * 16);
    const uint32_t bOff = (uint32_t)((wn + (lane >> 4) * 8 + (lane & 7)) * 80
                                     + ((lane >> 3) & 1) * 16);

    // global-load mappings
    int arow[2], ac[2];
#pragma unroll
    for (int p = 0; p < 2; p++) { int idx = tid + p * 256; arow[p] = idx >> 2; ac[p] = idx & 3; }
    int brow[2], bc[2];
#pragma unroll
    for (int p = 0; p < 2; p++) { int idx = tid + p * 256; brow[p] = idx >> 3; bc[p] = idx & 7; }

    uint4 pAh[2], pAl[2];
    float4 pW[2];

    // ---- prologue: LDG chunk 0, convert, STS -> stage 0 ----
#pragma unroll
    for (int p = 0; p < 2; p++) {
        size_t off = (size_t)(m0 + arow[p]) * INPUT + ac[p] * 8;
        pAh[p] = *(const uint4*)(g_Ahi + off);
        pAl[p] = *(const uint4*)(g_Alo + off);
        pW[p]  = *(const float4*)(W + (size_t)(n0 + brow[p]) * INPUT + bc[p] * 4);
    }
    {
        char* st = smem;
#pragma unroll
        for (int p = 0; p < 2; p++) {
            uint32_t d = arow[p] * 80 + ac[p] * 16;
            *(uint4*)(st + OFF_AH + d) = pAh[p];
            *(uint4*)(st + OFF_AL + d) = pAl[p];
            uint2 h, l;
            cvt_pair_h(pW[p].x, pW[p].y, h.x, l.x);
            cvt_pair_h(pW[p].z, pW[p].w, h.y, l.y);
            uint32_t e = brow[p] * 80 + bc[p] * 8;
            *(uint2*)(st + OFF_BH + e) = h;
            *(uint2*)(st + OFF_BL + e) = l;
        }
    }
    __syncthreads();

    int buf = 0;
    for (int c = 0; c < NCH; c++) {
        if (c + 1 < NCH) {
            int kb = (c + 1) * GK;
#pragma unroll
            for (int p = 0; p < 2; p++) {
                size_t off = (size_t)(m0 + arow[p]) * INPUT + kb + ac[p] * 8;
                pAh[p] = *(const uint4*)(g_Ahi + off);
                pAl[p] = *(const uint4*)(g_Alo + off);
                pW[p]  = *(const float4*)(W + (size_t)(n0 + brow[p]) * INPUT + kb + bc[p] * 4);
            }
        }

        // ---- compute on stage buf ----
        const uint32_t st = sbase + buf * STAGE_B;
#pragma unroll
        for (int kk = 0; kk < 2; kk++) {
            const uint32_t kb = kk * 32;
            uint32_t ah[2][4], al[2][4], bh[8], bl[8];
#pragma unroll
            for (int am = 0; am < 2; am++) {
                lm4(ah[am][0], ah[am][1], ah[am][2], ah[am][3],
                    st + OFF_AH + aOff + am * 1280 + kb);
                lm4(al[am][0], al[am][1], al[am][2], al[am][3],
                    st + OFF_AL + aOff + am * 1280 + kb);
            }
            lm4(bh[0], bh[1], bh[2], bh[3], st + OFF_BH + bOff + kb);
            lm4(bh[4], bh[5], bh[6], bh[7], st + OFF_BH + bOff + 1280 + kb);
            lm4(bl[0], bl[1], bl[2], bl[3], st + OFF_BL + bOff + kb);
            lm4(bl[4], bl[5], bl[6], bl[7], st + OFF_BL + bOff + 1280 + kb);
#pragma unroll
            for (int am = 0; am < 2; am++)
#pragma unroll
                for (int an = 0; an < 4; an++) {
                    mma_f16_f32acc(acc[am][an], ah[am], &bh[an * 2]);
                    mma_f16_f16acc(accC[am][an], ah[am], &bl[an * 2]);
                    mma_f16_f16acc(accC[am][an], al[am], &bh[an * 2]);
                }
        }

        // ---- convert + STS next chunk into other stage ----
        if (c + 1 < NCH) {
            char* sn = smem + (buf ^ 1) * STAGE_B;
#pragma unroll
            for (int p = 0; p < 2; p++) {
                uint32_t d = arow[p] * 80 + ac[p] * 16;
                *(uint4*)(sn + OFF_AH + d) = pAh[p];
                *(uint4*)(sn + OFF_AL + d) = pAl[p];
                uint2 h, l;
                cvt_pair_h(pW[p].x, pW[p].y, h.x, l.x);
                cvt_pair_h(pW[p].z, pW[p].w, h.y, l.y);
                uint32_t e = brow[p] * 80 + bc[p] * 8;
                *(uint2*)(sn + OFF_BH + e) = h;
                *(uint2*)(sn + OFF_BL + e) = l;
            }
            __syncthreads();
            buf ^= 1;
        }
    }

    // ---- epilogue: result = hh + corr/2048 + bias (D mapping validated R10/R11) ----
#pragma unroll
    for (int am = 0; am < 2; am++) {
        int m = m0 + wm + am * 16 + g;
#pragma unroll
        for (int an = 0; an < 4; an++) {
            int n = n0 + wn + an * 8 + tg * 2;
            float2 c01 = __half22float2(*reinterpret_cast<__half2*>(&accC[am][an][0]));
            float2 c23 = __half22float2(*reinterpret_cast<__half2*>(&accC[am][an][1]));
            float bi0 = b_ih[n]     + b_hh[n];
            float bi1 = b_ih[n + 1] + b_hh[n + 1];
            float2 v0 = make_float2(acc[am][an][0] + c01.x * INV_LO + bi0,
                                    acc[am][an][1] + c01.y * INV_LO + bi1);
            float2 v1 = make_float2(acc[am][an][2] + c23.x * INV_LO + bi0,
                                    acc[am][an][3] + c23.y * INV_LO + bi1);
            *(float2*)&g_xproj[(size_t)m * GATES + n]       = v0;
            *(float2*)&g_xproj[(size_t)(m + 8) * GATES + n] = v1;
        }
    }
}

// ---------------- persistent LSTM scan: payload epochs + clock-paced poll ----------------
#define SCAN_CTAS 128

__device__ __forceinline__ float fast_sigmoid(float x) {
    return __fdividef(1.f, 1.f + __expf(-x));
}
__device__ __forceinline__ float fast_tanh(float x) {
    float e = __expf(-2.f * x);
    return __fdividef(1.f - e, 1.f + e);
}
__device__ __forceinline__ unsigned long long ld_rlx(const unsigned long long* p) {
    unsigned long long v;
    asm volatile("ld.relaxed.gpu.global.u64 %0, [%1];" : "=l"(v) : "l"(p) : "memory");
    return v;
}
__device__ __forceinline__ void st_rlx(unsigned long long* p, unsigned long long v) {
    asm volatile("st.relaxed.gpu.global.u64 [%0], %1;" :: "l"(p), "l"(v) : "memory");
}

__global__ __launch_bounds__(256, 1)
void scan_kernel(const float* __restrict__ Whh) {
    __shared__ float hs[2][HID];

    const int tid  = threadIdx.x;
    const int warp = tid >> 5;
    const int lane = tid & 31;
    const int b    = blockIdx.x;
    const int j    = b * 8 + warp;

    unsigned long long wreg[4][8][2];
#pragma unroll
    for (int g = 0; g < 4; g++) {
        const float* wrow = Whh + (size_t)(g * HID + j) * HID;
#pragma unroll
        for (int i = 0; i < 8; i++) {
            ulonglong2 v = *(const ulonglong2*)&wrow[lane * 4 + i * 128];
            wreg[g][i][0] = v.x;
            wreg[g][i][1] = v.y;
        }
    }

    float cstate = 0.f;

    for (int t = 0; t < T_STEPS; t++) {
        float xg0 = __ldg(&g_xproj[(size_t)t * GATES + 0 * HID + j]);
        float xg1 = __ldg(&g_xproj[(size_t)t * GATES + 1 * HID + j]);
        float xg2 = __ldg(&g_xproj[(size_t)t * GATES + 2 * HID + j]);
        float xg3 = __ldg(&g_xproj[(size_t)t * GATES + 3 * HID + j]);

        const unsigned long long* p0 = g_hp[t & 1] + tid;
        const unsigned int want = (unsigned int)t;
        unsigned long long v0, v1, v2, v3;
        for (;;) {
            v0 = ld_rlx(p0);
            v1 = ld_rlx(p0 + 256);
            v2 = ld_rlx(p0 + 512);
            v3 = ld_rlx(p0 + 768);
            bool ok = ((unsigned int)(v0 >> 32) == want) &
                      ((unsigned int)(v1 >> 32) == want) &
                      ((unsigned int)(v2 >> 32) == want) &
                      ((unsigned int)(v3 >> 32) == want);
            if (ok) break;
            // pause ~150 cyc (zero memory traffic) so the L1tex/LSU queue
            // drains instead of being flooded by spin LDGs
            unsigned s = (unsigned)clock();
            while ((unsigned)clock() - s < 150u) { }
        }
        float* cur = hs[t & 1];
        cur[tid]       = __uint_as_float((unsigned int)v0);
        cur[tid + 256] = __uint_as_float((unsigned int)v1);
        cur[tid + 512] = __uint_as_float((unsigned int)v2);
        cur[tid + 768] = __uint_as_float((unsigned int)v3);
        __syncthreads();

        unsigned long long a2[4] = {0ULL, 0ULL, 0ULL, 0ULL};
#pragma unroll
        for (int i = 0; i < 8; i++) {
            ulonglong2 h2 = *(const ulonglong2*)&cur[lane * 4 + i * 128];
#pragma unroll
            for (int g = 0; g < 4; g++) {
                ffma2(a2[g], h2.x, wreg[g][i][0]);
                ffma2(a2[g], h2.y, wreg[g][i][1]);
            }
        }

        float red[4];
#pragma unroll
        for (int g = 0; g < 4; g++) {
            float lo, hi;
            unpack2(a2[g], lo, hi);
            red[g] = lo + hi;
        }
#pragma unroll
        for (int o = 16; o; o >>= 1) {
#pragma unroll
            for (int g = 0; g < 4; g++)
                red[g] += __shfl_xor_sync(0xffffffffu, red[g], o);
        }

        float gi = fast_sigmoid(xg0 + red[0]);
        float gf = fast_sigmoid(xg1 + red[1]);
        float gg = fast_tanh(xg2 + red[2]);
        float go = fast_sigmoid(xg3 + red[3]);
        cstate = gf * cstate + gi * gg;
        float hnew = go * fast_tanh(cstate);

        if (lane == 0) {
            unsigned long long pk =
                ((unsigned long long)(unsigned int)(t + 1) << 32) |
                (unsigned long long)__float_as_uint(hnew);
            st_rlx(&g_hp[(t + 1) & 1][j], pk);
        }
    }
}

// ---------------- final: out = h_T @ fc_w^T + fc_b ----------------
__global__ __launch_bounds__(256, 2)
void final_kernel(const float* __restrict__ fcw,
                  const float* __restrict__ fcb,
                  float* __restrict__ out) {
    __shared__ float hs[HID];
    const int tid = threadIdx.x, warp = tid >> 5, lane = tid & 31;
#pragma unroll
    for (int q = 0; q < 4; q++)
        hs[tid + q * 256] = __uint_as_float((unsigned int)g_hp[0][tid + q * 256]);
    __syncthreads();

    int row = blockIdx.x * 16 + warp * 2;
    const float* wr0 = fcw + (size_t)row * HID;
    const float* wr1 = wr0 + HID;
    float acc0 = 0.f, acc1 = 0.f;
#pragma unroll
    for (int i = 0; i < 8; i++) {
        float4 h4 = *(const float4*)&hs[lane * 4 + i * 128];
        float4 a4 = *(const float4*)&wr0[lane * 4 + i * 128];
        float4 b4 = *(const float4*)&wr1[lane * 4 + i * 128];
        acc0 += a4.x * h4.x + a4.y * h4.y + a4.z * h4.z + a4.w * h4.w;
        acc1 += b4.x * h4.x + b4.y * h4.y + b4.z * h4.z + b4.w * h4.w;
    }
#pragma unroll
    for (int o = 16; o; o >>= 1) {
        acc0 += __shfl_xor_sync(0xffffffffu, acc0, o);
        acc1 += __shfl_xor_sync(0xffffffffu, acc1, o);
    }
    if (lane == 0) {
        out[row]     = acc0 + fcb[row];
        out[row + 1] = acc1 + fcb[row + 1];
    }
}

// ---------------- launch ----------------
extern "C" void kernel_launch(void* const* d_in, const int* in_sizes, int n_in,
                              void* d_out, int out_size) {
    const float* frames = (const float*)d_in[0];
    const float* W_ih   = (const float*)d_in[1];
    const float* W_hh   = (const float*)d_in[2];
    const float* b_ih   = (const float*)d_in[3];
    const float* b_hh   = (const float*)d_in[4];
    const float* fc_w   = (const float*)d_in[5];
    const float* fc_b   = (const float*)d_in[6];
    float* out = (float*)d_out;

    cudaFuncSetAttribute(gemm_fused_kernel,
                         cudaFuncAttributeMaxDynamicSharedMemorySize, GEMM_SMEM);

    init_kernel<<<4, 256>>>();

    splitA_kernel<<<1024, 256>>>(frames);

    dim3 gg(GATES / 64, T_STEPS / 128);   // (64, 2) = 128 CTAs
    gemm_fused_kernel<<<gg, 256, GEMM_SMEM>>>(W_ih, b_ih, b_hh);

    scan_kernel<<<SCAN_CTAS, 256>>>(W_hh);

    final_kernel<<<12288 / 16, 256>>>(fc_w, fc_b, out);
}

// round 15
// speedup vs baseline: 1.3756x; 1.1947x over previous
#include <cuda_runtime.h>
#include <cuda_fp16.h>
#include <cstdint>
#include <math.h>

#define T_STEPS 256
#define INPUT   12288
#define HID     1024
#define GATES   4096

#define LO_SCALE 2048.0f
#define INV_LO   (1.0f / 2048.0f)

// ---------------- device scratch (no allocations allowed) ----------------
__device__ float              g_xproj[T_STEPS * GATES];  // 4 MB
__device__ unsigned long long g_hp[2][HID];              // {epoch|h} ping-pong
// fp16 hi + scaled-lo split of A (frames); W split in-kernel
__device__ __half g_Ahi[T_STEPS * INPUT];
__device__ __half g_Alo[T_STEPS * INPUT];

// ---------------- helpers: packed f32x2 FMA (scan) ----------------
__device__ __forceinline__ void ffma2(unsigned long long& d,
                                      unsigned long long a,
                                      unsigned long long b) {
    asm("fma.rn.f32x2 %0, %1, %2, %0;" : "+l"(d) : "l"(a), "l"(b));
}
__device__ __forceinline__ void unpack2(unsigned long long v, float& lo, float& hi) {
    asm("mov.b64 {%0, %1}, %2;" : "=f"(lo), "=f"(hi) : "l"(v));
}

// ---------------- init ----------------
__global__ void init_kernel() {
    int tid = blockIdx.x * blockDim.x + threadIdx.x;
    if (tid < HID) {
        g_hp[0][tid] = 0ULL;
        g_hp[1][tid] = 0ULL;
    }
}

// ---------------- fp16 split: hi = f16(x), lo = f16((x - hi) * 2048) ----------------
__device__ __forceinline__ void cvt_pair_h(float f0, float f1,
                                           unsigned int& h01, unsigned int& l01) {
    __half2 h = __floats2half2_rn(f0, f1);
    float e0 = (f0 - __half2float(__low2half(h)))  * LO_SCALE;
    float e1 = (f1 - __half2float(__high2half(h))) * LO_SCALE;
    __half2 l = __floats2half2_rn(e0, e1);
    h01 = *reinterpret_cast<unsigned int*>(&h);
    l01 = *reinterpret_cast<unsigned int*>(&l);
}
__global__ __launch_bounds__(256)
void splitA_kernel(const float* __restrict__ A) {
    const int NA = T_STEPS * INPUT / 4;
    int stride = gridDim.x * blockDim.x;
    for (int i = blockIdx.x * blockDim.x + threadIdx.x; i < NA; i += stride) {
        float4 v = ((const float4*)A)[i];
        uint2 hi, lo;
        cvt_pair_h(v.x, v.y, hi.x, lo.x);
        cvt_pair_h(v.z, v.w, hi.y, lo.y);
        ((uint2*)g_Ahi)[i] = hi;
        ((uint2*)g_Alo)[i] = lo;
    }
}

// ---------------- fused mma GEMM: x_proj = frames @ W_ih^T + biases ----------------
// CTA tile 128m x 64n, grid (64, 2). A pre-split fp16; W split in-kernel.
// Per k16: hh (f32 acc, exact main) + [hl + lh] (shared f16 acc, scaled 2048).
#define GK 32
#define NCH (INPUT / GK)        // 384 chunks
#define A_MAT_B (128 * 80)      // 10240 B (128 rows x 80B padded)
#define B_MAT_B (64 * 80)       //  5120 B
#define STAGE_B (2 * A_MAT_B + 2 * B_MAT_B)   // 30720
#define GEMM_SMEM (2 * STAGE_B)               // 61440
#define OFF_AH 0
#define OFF_AL A_MAT_B
#define OFF_BH (2 * A_MAT_B)
#define OFF_BL (2 * A_MAT_B + B_MAT_B)

__device__ __forceinline__ uint32_t smem_u32(const void* p) {
    uint32_t a;
    asm("{ .reg .u64 t; cvta.to.shared.u64 t, %1; cvt.u32.u64 %0, t; }" : "=r"(a) : "l"(p));
    return a;
}
__device__ __forceinline__ void lm4(uint32_t& d0, uint32_t& d1, uint32_t& d2,
                                    uint32_t& d3, uint32_t addr) {
    asm volatile("ldmatrix.sync.aligned.m8n8.x4.shared.b16 {%0,%1,%2,%3}, [%4];"
                 : "=r"(d0), "=r"(d1), "=r"(d2), "=r"(d3) : "r"(addr));
}
__device__ __forceinline__ void mma_f16_f32acc(float c[4], const uint32_t a[4],
                                               const uint32_t b[2]) {
    asm volatile(
        "mma.sync.aligned.m16n8k16.row.col.f32.f16.f16.f32 "
        "{%0,%1,%2,%3}, {%4,%5,%6,%7}, {%8,%9}, {%0,%1,%2,%3};"
        : "+f"(c[0]), "+f"(c[1]), "+f"(c[2]), "+f"(c[3])
        : "r"(a[0]), "r"(a[1]), "r"(a[2]), "r"(a[3]), "r"(b[0]), "r"(b[1]));
}
__device__ __forceinline__ void mma_f16_f16acc(uint32_t c[2], const uint32_t a[4],
                                               const uint32_t b[2]) {
    asm volatile(
        "mma.sync.aligned.m16n8k16.row.col.f16.f16.f16.f16 "
        "{%0,%1}, {%2,%3,%4,%5}, {%6,%7}, {%0,%1};"
        : "+r"(c[0]), "+r"(c[1])
        : "r"(a[0]), "r"(a[1]), "r"(a[2]), "r"(a[3]), "r"(b[0]), "r"(b[1]));
}

__global__ __launch_bounds__(256, 1)
void gemm_fused_kernel(const float* __restrict__ W,
                       const float* __restrict__ b_ih,
                       const float* __restrict__ b_hh) {
    extern __shared__ char smem[];
    const uint32_t sbase = smem_u32(smem);
    const int tid  = threadIdx.x;
    const int warp = tid >> 5;
    const int lane = tid & 31;
    const int g    = lane >> 2;
    const int tg   = lane & 3;
    const int n0   = blockIdx.x * 64;
    const int m0   = blockIdx.y * 128;
    const int wm   = (warp & 3) * 32;
    const int wn   = (warp >> 2) * 32;

    float    acc [2][4][4];   // main hh, f32
    uint32_t accC[2][4][2];   // corrections, f16x2 pairs
#pragma unroll
    for (int i = 0; i < 2; i++)
#pragma unroll
        for (int jn = 0; jn < 4; jn++) {
#pragma unroll
            for (int q = 0; q < 4; q++) acc[i][jn][q] = 0.f;
            accC[i][jn][0] = 0u; accC[i][jn][1] = 0u;
        }

    // ldmatrix per-lane offsets (validated in R11)
    const uint32_t aOff = (uint32_t)((wm + ((lane >> 3) & 1) * 8 + (lane & 7)) * 80
                                     + (lane >> 4) * 16);
    const uint32_t bOff = (uint32_t)((wn + (lane >> 4) * 8 + (lane & 7)) * 80
                                     + ((lane >> 3) & 1) * 16);

    // global-load mappings
    int arow[2], ac[2];
#pragma unroll
    for (int p = 0; p < 2; p++) { int idx = tid + p * 256; arow[p] = idx >> 2; ac[p] = idx & 3; }
    int brow[2], bc[2];
#pragma unroll
    for (int p = 0; p < 2; p++) { int idx = tid + p * 256; brow[p] = idx >> 3; bc[p] = idx & 7; }

    uint4 pAh[2], pAl[2];
    float4 pW[2];

    // ---- prologue: LDG chunk 0, convert, STS -> stage 0 ----
#pragma unroll
    for (int p = 0; p < 2; p++) {
        size_t off = (size_t)(m0 + arow[p]) * INPUT + ac[p] * 8;
        pAh[p] = *(const uint4*)(g_Ahi + off);
        pAl[p] = *(const uint4*)(g_Alo + off);
        pW[p]  = *(const float4*)(W + (size_t)(n0 + brow[p]) * INPUT + bc[p] * 4);
    }
    {
        char* st = smem;
#pragma unroll
        for (int p = 0; p < 2; p++) {
            uint32_t d = arow[p] * 80 + ac[p] * 16;
            *(uint4*)(st + OFF_AH + d) = pAh[p];
            *(uint4*)(st + OFF_AL + d) = pAl[p];
            uint2 h, l;
            cvt_pair_h(pW[p].x, pW[p].y, h.x, l.x);
            cvt_pair_h(pW[p].z, pW[p].w, h.y, l.y);
            uint32_t e = brow[p] * 80 + bc[p] * 8;
            *(uint2*)(st + OFF_BH + e) = h;
            *(uint2*)(st + OFF_BL + e) = l;
        }
    }
    __syncthreads();

    int buf = 0;
    for (int c = 0; c < NCH; c++) {
        if (c + 1 < NCH) {
            int kb = (c + 1) * GK;
#pragma unroll
            for (int p = 0; p < 2; p++) {
                size_t off = (size_t)(m0 + arow[p]) * INPUT + kb + ac[p] * 8;
                pAh[p] = *(const uint4*)(g_Ahi + off);
                pAl[p] = *(const uint4*)(g_Alo + off);
                pW[p]  = *(const float4*)(W + (size_t)(n0 + brow[p]) * INPUT + kb + bc[p] * 4);
            }
        }

        // ---- compute on stage buf ----
        const uint32_t st = sbase + buf * STAGE_B;
#pragma unroll
        for (int kk = 0; kk < 2; kk++) {
            const uint32_t kb = kk * 32;
            uint32_t ah[2][4], al[2][4], bh[8], bl[8];
#pragma unroll
            for (int am = 0; am < 2; am++) {
                lm4(ah[am][0], ah[am][1], ah[am][2], ah[am][3],
                    st + OFF_AH + aOff + am * 1280 + kb);
                lm4(al[am][0], al[am][1], al[am][2], al[am][3],
                    st + OFF_AL + aOff + am * 1280 + kb);
            }
            lm4(bh[0], bh[1], bh[2], bh[3], st + OFF_BH + bOff + kb);
            lm4(bh[4], bh[5], bh[6], bh[7], st + OFF_BH + bOff + 1280 + kb);
            lm4(bl[0], bl[1], bl[2], bl[3], st + OFF_BL + bOff + kb);
            lm4(bl[4], bl[5], bl[6], bl[7], st + OFF_BL + bOff + 1280 + kb);
#pragma unroll
            for (int am = 0; am < 2; am++)
#pragma unroll
                for (int an = 0; an < 4; an++) {
                    mma_f16_f32acc(acc[am][an], ah[am], &bh[an * 2]);
                    mma_f16_f16acc(accC[am][an], ah[am], &bl[an * 2]);
                    mma_f16_f16acc(accC[am][an], al[am], &bh[an * 2]);
                }
        }

        // ---- convert + STS next chunk into other stage ----
        if (c + 1 < NCH) {
            char* sn = smem + (buf ^ 1) * STAGE_B;
#pragma unroll
            for (int p = 0; p < 2; p++) {
                uint32_t d = arow[p] * 80 + ac[p] * 16;
                *(uint4*)(sn + OFF_AH + d) = pAh[p];
                *(uint4*)(sn + OFF_AL + d) = pAl[p];
                uint2 h, l;
                cvt_pair_h(pW[p].x, pW[p].y, h.x, l.x);
                cvt_pair_h(pW[p].z, pW[p].w, h.y, l.y);
                uint32_t e = brow[p] * 80 + bc[p] * 8;
                *(uint2*)(sn + OFF_BH + e) = h;
                *(uint2*)(sn + OFF_BL + e) = l;
            }
            __syncthreads();
            buf ^= 1;
        }
    }

    // ---- epilogue: result = hh + corr/2048 + bias ----
#pragma unroll
    for (int am = 0; am < 2; am++) {
        int m = m0 + wm + am * 16 + g;
#pragma unroll
        for (int an = 0; an < 4; an++) {
            int n = n0 + wn + an * 8 + tg * 2;
            float2 c01 = __half22float2(*reinterpret_cast<__half2*>(&accC[am][an][0]));
            float2 c23 = __half22float2(*reinterpret_cast<__half2*>(&accC[am][an][1]));
            float bi0 = b_ih[n]     + b_hh[n];
            float bi1 = b_ih[n + 1] + b_hh[n + 1];
            float2 v0 = make_float2(acc[am][an][0] + c01.x * INV_LO + bi0,
                                    acc[am][an][1] + c01.y * INV_LO + bi1);
            float2 v1 = make_float2(acc[am][an][2] + c23.x * INV_LO + bi0,
                                    acc[am][an][3] + c23.y * INV_LO + bi1);
            *(float2*)&g_xproj[(size_t)m * GATES + n]       = v0;
            *(float2*)&g_xproj[(size_t)(m + 8) * GATES + n] = v1;
        }
    }
}

// ---------------- persistent LSTM scan: R5/R11 verbatim (busy-spin payload poll) ----------------
#define SCAN_CTAS 128

__device__ __forceinline__ float fast_sigmoid(float x) {
    return __fdividef(1.f, 1.f + __expf(-x));
}
__device__ __forceinline__ float fast_tanh(float x) {
    float e = __expf(-2.f * x);
    return __fdividef(1.f - e, 1.f + e);
}
__device__ __forceinline__ unsigned long long ld_rlx(const unsigned long long* p) {
    unsigned long long v;
    asm volatile("ld.relaxed.gpu.global.u64 %0, [%1];" : "=l"(v) : "l"(p) : "memory");
    return v;
}
__device__ __forceinline__ void st_rlx(unsigned long long* p, unsigned long long v) {
    asm volatile("st.relaxed.gpu.global.u64 [%0], %1;" :: "l"(p), "l"(v) : "memory");
}

__global__ __launch_bounds__(256, 1)
void scan_kernel(const float* __restrict__ Whh) {
    __shared__ float hs[2][HID];

    const int tid  = threadIdx.x;
    const int warp = tid >> 5;
    const int lane = tid & 31;
    const int b    = blockIdx.x;
    const int j    = b * 8 + warp;

    unsigned long long wreg[4][8][2];
#pragma unroll
    for (int g = 0; g < 4; g++) {
        const float* wrow = Whh + (size_t)(g * HID + j) * HID;
#pragma unroll
        for (int i = 0; i < 8; i++) {
            ulonglong2 v = *(const ulonglong2*)&wrow[lane * 4 + i * 128];
            wreg[g][i][0] = v.x;
            wreg[g][i][1] = v.y;
        }
    }

    float cstate = 0.f;

    for (int t = 0; t < T_STEPS; t++) {
        float xg0 = __ldg(&g_xproj[(size_t)t * GATES + 0 * HID + j]);
        float xg1 = __ldg(&g_xproj[(size_t)t * GATES + 1 * HID + j]);
        float xg2 = __ldg(&g_xproj[(size_t)t * GATES + 2 * HID + j]);
        float xg3 = __ldg(&g_xproj[(size_t)t * GATES + 3 * HID + j]);

        const unsigned long long* p0 = g_hp[t & 1] + tid;
        const unsigned int want = (unsigned int)t;
        unsigned long long v0, v1, v2, v3;
        bool ok;
        do {
            v0 = ld_rlx(p0);
            v1 = ld_rlx(p0 + 256);
            v2 = ld_rlx(p0 + 512);
            v3 = ld_rlx(p0 + 768);
            ok = ((unsigned int)(v0 >> 32) == want) &
                 ((unsigned int)(v1 >> 32) == want) &
                 ((unsigned int)(v2 >> 32) == want) &
                 ((unsigned int)(v3 >> 32) == want);
        } while (!ok);
        float* cur = hs[t & 1];
        cur[tid]       = __uint_as_float((unsigned int)v0);
        cur[tid + 256] = __uint_as_float((unsigned int)v1);
        cur[tid + 512] = __uint_as_float((unsigned int)v2);
        cur[tid + 768] = __uint_as_float((unsigned int)v3);
        __syncthreads();

        unsigned long long a2[4] = {0ULL, 0ULL, 0ULL, 0ULL};
#pragma unroll
        for (int i = 0; i < 8; i++) {
            ulonglong2 h2 = *(const ulonglong2*)&cur[lane * 4 + i * 128];
#pragma unroll
            for (int g = 0; g < 4; g++) {
                ffma2(a2[g], h2.x, wreg[g][i][0]);
                ffma2(a2[g], h2.y, wreg[g][i][1]);
            }
        }

        float red[4];
#pragma unroll
        for (int g = 0; g < 4; g++) {
            float lo, hi;
            unpack2(a2[g], lo, hi);
            red[g] = lo + hi;
        }
#pragma unroll
        for (int o = 16; o; o >>= 1) {
#pragma unroll
            for (int g = 0; g < 4; g++)
                red[g] += __shfl_xor_sync(0xffffffffu, red[g], o);
        }

        float gi = fast_sigmoid(xg0 + red[0]);
        float gf = fast_sigmoid(xg1 + red[1]);
        float gg = fast_tanh(xg2 + red[2]);
        float go = fast_sigmoid(xg3 + red[3]);
        cstate = gf * cstate + gi * gg;
        float hnew = go * fast_tanh(cstate);

        if (lane == 0) {
            unsigned long long pk =
                ((unsigned long long)(unsigned int)(t + 1) << 32) |
                (unsigned long long)__float_as_uint(hnew);
            st_rlx(&g_hp[(t + 1) & 1][j], pk);
        }
    }
}

// ---------------- final: out = h_T @ fc_w^T + fc_b ----------------
__global__ __launch_bounds__(256, 2)
void final_kernel(const float* __restrict__ fcw,
                  const float* __restrict__ fcb,
                  float* __restrict__ out) {
    __shared__ float hs[HID];
    const int tid = threadIdx.x, warp = tid >> 5, lane = tid & 31;
#pragma unroll
    for (int q = 0; q < 4; q++)
        hs[tid + q * 256] = __uint_as_float((unsigned int)g_hp[0][tid + q * 256]);
    __syncthreads();

    int row = blockIdx.x * 16 + warp * 2;
    const float* wr0 = fcw + (size_t)row * HID;
    const float* wr1 = wr0 + HID;
    float acc0 = 0.f, acc1 = 0.f;
#pragma unroll
    for (int i = 0; i < 8; i++) {
        float4 h4 = *(const float4*)&hs[lane * 4 + i * 128];
        float4 a4 = *(const float4*)&wr0[lane * 4 + i * 128];
        float4 b4 = *(const float4*)&wr1[lane * 4 + i * 128];
        acc0 += a4.x * h4.x + a4.y * h4.y + a4.z * h4.z + a4.w * h4.w;
        acc1 += b4.x * h4.x + b4.y * h4.y + b4.z * h4.z + b4.w * h4.w;
    }
#pragma unroll
    for (int o = 16; o; o >>= 1) {
        acc0 += __shfl_xor_sync(0xffffffffu, acc0, o);
        acc1 += __shfl_xor_sync(0xffffffffu, acc1, o);
    }
    if (lane == 0) {
        out[row]     = acc0 + fcb[row];
        out[row + 1] = acc1 + fcb[row + 1];
    }
}

// ---------------- launch ----------------
extern "C" void kernel_launch(void* const* d_in, const int* in_sizes, int n_in,
                              void* d_out, int out_size) {
    const float* frames = (const float*)d_in[0];
    const float* W_ih   = (const float*)d_in[1];
    const float* W_hh   = (const float*)d_in[2];
    const float* b_ih   = (const float*)d_in[3];
    const float* b_hh   = (const float*)d_in[4];
    const float* fc_w   = (const float*)d_in[5];
    const float* fc_b   = (const float*)d_in[6];
    float* out = (float*)d_out;

    cudaFuncSetAttribute(gemm_fused_kernel,
                         cudaFuncAttributeMaxDynamicSharedMemorySize, GEMM_SMEM);

    init_kernel<<<4, 256>>>();

    splitA_kernel<<<1024, 256>>>(frames);

    dim3 gg(GATES / 64, T_STEPS / 128);   // (64, 2) = 128 CTAs
    gemm_fused_kernel<<<gg, 256, GEMM_SMEM>>>(W_ih, b_ih, b_hh);

    scan_kernel<<<SCAN_CTAS, 256>>>(W_hh);

    final_kernel<<<12288 / 16, 256>>>(fc_w, fc_b, out);
}

// round 16
// speedup vs baseline: 1.4668x; 1.0663x over previous
#include <cuda_runtime.h>
#include <cuda_fp16.h>
#include <cstdint>
#include <math.h>

#define T_STEPS 256
#define INPUT   12288
#define HID     1024
#define GATES   4096

#define LO_SCALE 2048.0f
#define INV_LO   (1.0f / 2048.0f)

// ---------------- device scratch (no allocations allowed) ----------------
__device__ float              g_xproj[T_STEPS * GATES];  // 4 MB
__device__ unsigned long long g_hp[2][HID];              // {epoch|h} ping-pong
// fp16 hi of A (frames); A-lo dropped (correction term al*bh omitted)
__device__ __half g_Ahi[T_STEPS * INPUT];

// ---------------- helpers: packed f32x2 FMA (scan) ----------------
__device__ __forceinline__ void ffma2(unsigned long long& d,
                                      unsigned long long a,
                                      unsigned long long b) {
    asm("fma.rn.f32x2 %0, %1, %2, %0;" : "+l"(d) : "l"(a), "l"(b));
}
__device__ __forceinline__ void unpack2(unsigned long long v, float& lo, float& hi) {
    asm("mov.b64 {%0, %1}, %2;" : "=f"(lo), "=f"(hi) : "l"(v));
}

// ---------------- fp16 split helpers ----------------
__device__ __forceinline__ void cvt_pair_h(float f0, float f1,
                                           unsigned int& h01, unsigned int& l01) {
    __half2 h = __floats2half2_rn(f0, f1);
    float e0 = (f0 - __half2float(__low2half(h)))  * LO_SCALE;
    float e1 = (f1 - __half2float(__high2half(h))) * LO_SCALE;
    __half2 l = __floats2half2_rn(e0, e1);
    h01 = *reinterpret_cast<unsigned int*>(&h);
    l01 = *reinterpret_cast<unsigned int*>(&l);
}
__device__ __forceinline__ unsigned int cvt_hi2(float f0, float f1) {
    __half2 h = __floats2half2_rn(f0, f1);
    return *reinterpret_cast<unsigned int*>(&h);
}

// ---------------- splitA (+ init of h buffers) ----------------
__global__ __launch_bounds__(256)
void splitA_kernel(const float* __restrict__ A) {
    const int NA = T_STEPS * INPUT / 4;
    int gid = blockIdx.x * blockDim.x + threadIdx.x;
    if (gid < HID) { g_hp[0][gid] = 0ULL; g_hp[1][gid] = 0ULL; }
    int stride = gridDim.x * blockDim.x;
    for (int i = gid; i < NA; i += stride) {
        float4 v = ((const float4*)A)[i];
        uint2 hi;
        hi.x = cvt_hi2(v.x, v.y);
        hi.y = cvt_hi2(v.z, v.w);
        ((uint2*)g_Ahi)[i] = hi;
    }
}

// ---------------- fused mma GEMM: x_proj = frames @ W_ih^T + biases ----------------
// CTA tile 128m x 64n, grid (64, 2). A hi-only fp16; W split hi/lo in-kernel.
// Per k16: hh (f32 acc) + hl (f16 acc, W-lo scaled 2048). al*bh dropped.
#define GK 32
#define NCH (INPUT / GK)        // 384 chunks
#define A_MAT_B (128 * 80)      // 10240 B (128 rows x 80B padded)
#define B_MAT_B (64 * 80)       //  5120 B
#define STAGE_B (A_MAT_B + 2 * B_MAT_B)       // 20480
#define GEMM_SMEM (2 * STAGE_B)               // 40960
#define OFF_AH 0
#define OFF_BH A_MAT_B
#define OFF_BL (A_MAT_B + B_MAT_B)

__device__ __forceinline__ uint32_t smem_u32(const void* p) {
    uint32_t a;
    asm("{ .reg .u64 t; cvta.to.shared.u64 t, %1; cvt.u32.u64 %0, t; }" : "=r"(a) : "l"(p));
    return a;
}
__device__ __forceinline__ void lm4(uint32_t& d0, uint32_t& d1, uint32_t& d2,
                                    uint32_t& d3, uint32_t addr) {
    asm volatile("ldmatrix.sync.aligned.m8n8.x4.shared.b16 {%0,%1,%2,%3}, [%4];"
                 : "=r"(d0), "=r"(d1), "=r"(d2), "=r"(d3) : "r"(addr));
}
__device__ __forceinline__ void mma_f16_f32acc(float c[4], const uint32_t a[4],
                                               const uint32_t b[2]) {
    asm volatile(
        "mma.sync.aligned.m16n8k16.row.col.f32.f16.f16.f32 "
        "{%0,%1,%2,%3}, {%4,%5,%6,%7}, {%8,%9}, {%0,%1,%2,%3};"
        : "+f"(c[0]), "+f"(c[1]), "+f"(c[2]), "+f"(c[3])
        : "r"(a[0]), "r"(a[1]), "r"(a[2]), "r"(a[3]), "r"(b[0]), "r"(b[1]));
}
__device__ __forceinline__ void mma_f16_f16acc(uint32_t c[2], const uint32_t a[4],
                                               const uint32_t b[2]) {
    asm volatile(
        "mma.sync.aligned.m16n8k16.row.col.f16.f16.f16.f16 "
        "{%0,%1}, {%2,%3,%4,%5}, {%6,%7}, {%0,%1};"
        : "+r"(c[0]), "+r"(c[1])
        : "r"(a[0]), "r"(a[1]), "r"(a[2]), "r"(a[3]), "r"(b[0]), "r"(b[1]));
}

__global__ __launch_bounds__(256, 1)
void gemm_fused_kernel(const float* __restrict__ W,
                       const float* __restrict__ b_ih,
                       const float* __restrict__ b_hh) {
    extern __shared__ char smem[];
    const uint32_t sbase = smem_u32(smem);
    const int tid  = threadIdx.x;
    const int warp = tid >> 5;
    const int lane = tid & 31;
    const int g    = lane >> 2;
    const int tg   = lane & 3;
    const int n0   = blockIdx.x * 64;
    const int m0   = blockIdx.y * 128;
    const int wm   = (warp & 3) * 32;
    const int wn   = (warp >> 2) * 32;

    float    acc [2][4][4];   // main hh, f32
    uint32_t accC[2][4][2];   // correction ah*bl, f16x2 pairs
#pragma unroll
    for (int i = 0; i < 2; i++)
#pragma unroll
        for (int jn = 0; jn < 4; jn++) {
#pragma unroll
            for (int q = 0; q < 4; q++) acc[i][jn][q] = 0.f;
            accC[i][jn][0] = 0u; accC[i][jn][1] = 0u;
        }

    // ldmatrix per-lane offsets (validated R11/R14)
    const uint32_t aOff = (uint32_t)((wm + ((lane >> 3) & 1) * 8 + (lane & 7)) * 80
                                     + (lane >> 4) * 16);
    const uint32_t bOff = (uint32_t)((wn + (lane >> 4) * 8 + (lane & 7)) * 80
                                     + ((lane >> 3) & 1) * 16);

    // global-load mappings
    int arow[2], ac[2];
#pragma unroll
    for (int p = 0; p < 2; p++) { int idx = tid + p * 256; arow[p] = idx >> 2; ac[p] = idx & 3; }
    int brow[2], bc[2];
#pragma unroll
    for (int p = 0; p < 2; p++) { int idx = tid + p * 256; brow[p] = idx >> 3; bc[p] = idx & 7; }

    uint4 pAh[2];
    float4 pW[2];

    // ---- prologue: LDG chunk 0, convert, STS -> stage 0 ----
#pragma unroll
    for (int p = 0; p < 2; p++) {
        pAh[p] = *(const uint4*)(g_Ahi + (size_t)(m0 + arow[p]) * INPUT + ac[p] * 8);
        pW[p]  = *(const float4*)(W + (size_t)(n0 + brow[p]) * INPUT + bc[p] * 4);
    }
    {
        char* st = smem;
#pragma unroll
        for (int p = 0; p < 2; p++) {
            uint32_t d = arow[p] * 80 + ac[p] * 16;
            *(uint4*)(st + OFF_AH + d) = pAh[p];
            uint2 h, l;
            cvt_pair_h(pW[p].x, pW[p].y, h.x, l.x);
            cvt_pair_h(pW[p].z, pW[p].w, h.y, l.y);
            uint32_t e = brow[p] * 80 + bc[p] * 8;
            *(uint2*)(st + OFF_BH + e) = h;
            *(uint2*)(st + OFF_BL + e) = l;
        }
    }
    __syncthreads();

    int buf = 0;
    for (int c = 0; c < NCH; c++) {
        if (c + 1 < NCH) {
            int kb = (c + 1) * GK;
#pragma unroll
            for (int p = 0; p < 2; p++) {
                pAh[p] = *(const uint4*)(g_Ahi + (size_t)(m0 + arow[p]) * INPUT + kb + ac[p] * 8);
                pW[p]  = *(const float4*)(W + (size_t)(n0 + brow[p]) * INPUT + kb + bc[p] * 4);
            }
        }

        // ---- compute on stage buf ----
        const uint32_t st = sbase + buf * STAGE_B;
#pragma unroll
        for (int kk = 0; kk < 2; kk++) {
            const uint32_t kb = kk * 32;
            uint32_t ah[2][4], bh[8], bl[8];
#pragma unroll
            for (int am = 0; am < 2; am++)
                lm4(ah[am][0], ah[am][1], ah[am][2], ah[am][3],
                    st + OFF_AH + aOff + am * 1280 + kb);
            lm4(bh[0], bh[1], bh[2], bh[3], st + OFF_BH + bOff + kb);
            lm4(bh[4], bh[5], bh[6], bh[7], st + OFF_BH + bOff + 1280 + kb);
            lm4(bl[0], bl[1], bl[2], bl[3], st + OFF_BL + bOff + kb);
            lm4(bl[4], bl[5], bl[6], bl[7], st + OFF_BL + bOff + 1280 + kb);
#pragma unroll
            for (int am = 0; am < 2; am++)
#pragma unroll
                for (int an = 0; an < 4; an++) {
                    mma_f16_f32acc(acc[am][an], ah[am], &bh[an * 2]);
                    mma_f16_f16acc(accC[am][an], ah[am], &bl[an * 2]);
                }
        }

        // ---- convert + STS next chunk into other stage ----
        if (c + 1 < NCH) {
            char* sn = smem + (buf ^ 1) * STAGE_B;
#pragma unroll
            for (int p = 0; p < 2; p++) {
                uint32_t d = arow[p] * 80 + ac[p] * 16;
                *(uint4*)(sn + OFF_AH + d) = pAh[p];
                uint2 h, l;
                cvt_pair_h(pW[p].x, pW[p].y, h.x, l.x);
                cvt_pair_h(pW[p].z, pW[p].w, h.y, l.y);
                uint32_t e = brow[p] * 80 + bc[p] * 8;
                *(uint2*)(sn + OFF_BH + e) = h;
                *(uint2*)(sn + OFF_BL + e) = l;
            }
            __syncthreads();
            buf ^= 1;
        }
    }

    // ---- epilogue: result = hh + corr/2048 + bias ----
#pragma unroll
    for (int am = 0; am < 2; am++) {
        int m = m0 + wm + am * 16 + g;
#pragma unroll
        for (int an = 0; an < 4; an++) {
            int n = n0 + wn + an * 8 + tg * 2;
            float2 c01 = __half22float2(*reinterpret_cast<__half2*>(&accC[am][an][0]));
            float2 c23 = __half22float2(*reinterpret_cast<__half2*>(&accC[am][an][1]));
            float bi0 = b_ih[n]     + b_hh[n];
            float bi1 = b_ih[n + 1] + b_hh[n + 1];
            float2 v0 = make_float2(acc[am][an][0] + c01.x * INV_LO + bi0,
                                    acc[am][an][1] + c01.y * INV_LO + bi1);
            float2 v1 = make_float2(acc[am][an][2] + c23.x * INV_LO + bi0,
                                    acc[am][an][3] + c23.y * INV_LO + bi1);
            *(float2*)&g_xproj[(size_t)m * GATES + n]       = v0;
            *(float2*)&g_xproj[(size_t)(m + 8) * GATES + n] = v1;
        }
    }
}

// ---------------- persistent LSTM scan: R5/R11/R15 verbatim (busy-spin) ----------------
#define SCAN_CTAS 128

__device__ __forceinline__ float fast_sigmoid(float x) {
    return __fdividef(1.f, 1.f + __expf(-x));
}
__device__ __forceinline__ float fast_tanh(float x) {
    float e = __expf(-2.f * x);
    return __fdividef(1.f - e, 1.f + e);
}
__device__ __forceinline__ unsigned long long ld_rlx(const unsigned long long* p) {
    unsigned long long v;
    asm volatile("ld.relaxed.gpu.global.u64 %0, [%1];" : "=l"(v) : "l"(p) : "memory");
    return v;
}
__device__ __forceinline__ void st_rlx(unsigned long long* p, unsigned long long v) {
    asm volatile("st.relaxed.gpu.global.u64 [%0], %1;" :: "l"(p), "l"(v) : "memory");
}

__global__ __launch_bounds__(256, 1)
void scan_kernel(const float* __restrict__ Whh) {
    __shared__ float hs[2][HID];

    const int tid  = threadIdx.x;
    const int warp = tid >> 5;
    const int lane = tid & 31;
    const int b    = blockIdx.x;
    const int j    = b * 8 + warp;

    unsigned long long wreg[4][8][2];
#pragma unroll
    for (int g = 0; g < 4; g++) {
        const float* wrow = Whh + (size_t)(g * HID + j) * HID;
#pragma unroll
        for (int i = 0; i < 8; i++) {
            ulonglong2 v = *(const ulonglong2*)&wrow[lane * 4 + i * 128];
            wreg[g][i][0] = v.x;
            wreg[g][i][1] = v.y;
        }
    }

    float cstate = 0.f;

    for (int t = 0; t < T_STEPS; t++) {
        float xg0 = __ldg(&g_xproj[(size_t)t * GATES + 0 * HID + j]);
        float xg1 = __ldg(&g_xproj[(size_t)t * GATES + 1 * HID + j]);
        float xg2 = __ldg(&g_xproj[(size_t)t * GATES + 2 * HID + j]);
        float xg3 = __ldg(&g_xproj[(size_t)t * GATES + 3 * HID + j]);

        const unsigned long long* p0 = g_hp[t & 1] + tid;
        const unsigned int want = (unsigned int)t;
        unsigned long long v0, v1, v2, v3;
        bool ok;
        do {
            v0 = ld_rlx(p0);
            v1 = ld_rlx(p0 + 256);
            v2 = ld_rlx(p0 + 512);
            v3 = ld_rlx(p0 + 768);
            ok = ((unsigned int)(v0 >> 32) == want) &
                 ((unsigned int)(v1 >> 32) == want) &
                 ((unsigned int)(v2 >> 32) == want) &
                 ((unsigned int)(v3 >> 32) == want);
        } while (!ok);
        float* cur = hs[t & 1];
        cur[tid]       = __uint_as_float((unsigned int)v0);
        cur[tid + 256] = __uint_as_float((unsigned int)v1);
        cur[tid + 512] = __uint_as_float((unsigned int)v2);
        cur[tid + 768] = __uint_as_float((unsigned int)v3);
        __syncthreads();

        unsigned long long a2[4] = {0ULL, 0ULL, 0ULL, 0ULL};
#pragma unroll
        for (int i = 0; i < 8; i++) {
            ulonglong2 h2 = *(const ulonglong2*)&cur[lane * 4 + i * 128];
#pragma unroll
            for (int g = 0; g < 4; g++) {
                ffma2(a2[g], h2.x, wreg[g][i][0]);
                ffma2(a2[g], h2.y, wreg[g][i][1]);
            }
        }

        float red[4];
#pragma unroll
        for (int g = 0; g < 4; g++) {
            float lo, hi;
            unpack2(a2[g], lo, hi);
            red[g] = lo + hi;
        }
#pragma unroll
        for (int o = 16; o; o >>= 1) {
#pragma unroll
            for (int g = 0; g < 4; g++)
                red[g] += __shfl_xor_sync(0xffffffffu, red[g], o);
        }

        float gi = fast_sigmoid(xg0 + red[0]);
        float gf = fast_sigmoid(xg1 + red[1]);
        float gg = fast_tanh(xg2 + red[2]);
        float go = fast_sigmoid(xg3 + red[3]);
        cstate = gf * cstate + gi * gg;
        float hnew = go * fast_tanh(cstate);

        if (lane == 0) {
            unsigned long long pk =
                ((unsigned long long)(unsigned int)(t + 1) << 32) |
                (unsigned long long)__float_as_uint(hnew);
            st_rlx(&g_hp[(t + 1) & 1][j], pk);
        }
    }
}

// ---------------- final: out = h_T @ fc_w^T + fc_b ----------------
__global__ __launch_bounds__(256, 2)
void final_kernel(const float* __restrict__ fcw,
                  const float* __restrict__ fcb,
                  float* __restrict__ out) {
    __shared__ float hs[HID];
    const int tid = threadIdx.x, warp = tid >> 5, lane = tid & 31;
#pragma unroll
    for (int q = 0; q < 4; q++)
        hs[tid + q * 256] = __uint_as_float((unsigned int)g_hp[0][tid + q * 256]);
    __syncthreads();

    int row = blockIdx.x * 16 + warp * 2;
    const float* wr0 = fcw + (size_t)row * HID;
    const float* wr1 = wr0 + HID;
    float acc0 = 0.f, acc1 = 0.f;
#pragma unroll
    for (int i = 0; i < 8; i++) {
        float4 h4 = *(const float4*)&hs[lane * 4 + i * 128];
        float4 a4 = *(const float4*)&wr0[lane * 4 + i * 128];
        float4 b4 = *(const float4*)&wr1[lane * 4 + i * 128];
        acc0 += a4.x * h4.x + a4.y * h4.y + a4.z * h4.z + a4.w * h4.w;
        acc1 += b4.x * h4.x + b4.y * h4.y + b4.z * h4.z + b4.w * h4.w;
    }
#pragma unroll
    for (int o = 16; o; o >>= 1) {
        acc0 += __shfl_xor_sync(0xffffffffu, acc0, o);
        acc1 += __shfl_xor_sync(0xffffffffu, acc1, o);
    }
    if (lane == 0) {
        out[row]     = acc0 + fcb[row];
        out[row + 1] = acc1 + fcb[row + 1];
    }
}

// ---------------- launch ----------------
extern "C" void kernel_launch(void* const* d_in, const int* in_sizes, int n_in,
                              void* d_out, int out_size) {
    const float* frames = (const float*)d_in[0];
    const float* W_ih   = (const float*)d_in[1];
    const float* W_hh   = (const float*)d_in[2];
    const float* b_ih   = (const float*)d_in[3];
    const float* b_hh   = (const float*)d_in[4];
    const float* fc_w   = (const float*)d_in[5];
    const float* fc_b   = (const float*)d_in[6];
    float* out = (float*)d_out;

    cudaFuncSetAttribute(gemm_fused_kernel,
                         cudaFuncAttributeMaxDynamicSharedMemorySize, GEMM_SMEM);

    splitA_kernel<<<1024, 256>>>(frames);   // also zeroes g_hp epochs

    dim3 gg(GATES / 64, T_STEPS / 128);     // (64, 2) = 128 CTAs
    gemm_fused_kernel<<<gg, 256, GEMM_SMEM>>>(W_ih, b_ih, b_hh);

    scan_kernel<<<SCAN_CTAS, 256>>>(W_hh);

    final_kernel<<<12288 / 16, 256>>>(fc_w, fc_b, out);
}